// round 16
// baseline (speedup 1.0000x reference)
#include <cuda_runtime.h>
#include <cuda_bf16.h>
#include <cstdint>

#define NLAYERS 6
#define B_TOTAL 131072
#define MROWS   32

// output layout: h_final [B,256] then aligns[6,B,3], divs[6,B,3], tens[6,B,3]
#define OUT_ALIGN 33554432
#define OUT_DIV   35913728
#define OUT_TEN   38273024

// SMEM byte offsets
#define SB_BUF  0        // 2 x 20480 : W chunk [256 n][pitch 40 bf16 = 80 B]
#define SB_HHI  40960    // 32 rows x 528 B : h/z hi plane (pitch 264 bf16)
#define SB_HLO  57856    // lo plane
#define SB_C1   74752    // 256 x float4 (a0, a1, a2, b1)
#define SB_B2   78848    // 256 floats
#define SB_STAT 79872    // 2 bufs x 128 floats (ss,d0,d1,d2 x 32 rows)
#define SB_SROW 80896    // 32 floats deferred clip scale
#define SMEM_DYN 81024

// W pre-split: [mat 2][split 2 (hi,lo)][n 256][k 256] bf16
__device__ __align__(16) __nv_bfloat16 g_Wb[262144];
__device__ __align__(16) float4 g_c1[256];   // normalized anchors (a0,a1,a2,0)

// ---------------------------------------------------------------- helpers
__device__ __forceinline__ uint32_t smem_u32(const void* p) {
    uint32_t a;
    asm("{ .reg .u64 t; cvta.to.shared.u64 t, %1; cvt.u32.u64 %0, t; }" : "=r"(a) : "l"(p));
    return a;
}
__device__ __forceinline__ float fast_tanh(float x) {
    float a = fabsf(x);
    float t = __expf(-2.0f * a);
    float r = __fdividef(1.0f - t, 1.0f + t);
    return copysignf(r, x);
}
__device__ __forceinline__ void split2(float x0, float x1, uint32_t& hi, uint32_t& lo) {
    __nv_bfloat16 h0 = __float2bfloat16(x0), h1 = __float2bfloat16(x1);
    float l0 = x0 - __bfloat162float(h0), l1 = x1 - __bfloat162float(h1);
    __nv_bfloat16 L0 = __float2bfloat16(l0), L1 = __float2bfloat16(l1);
    hi = (uint32_t)__bfloat16_as_ushort(h0) | ((uint32_t)__bfloat16_as_ushort(h1) << 16);
    lo = (uint32_t)__bfloat16_as_ushort(L0) | ((uint32_t)__bfloat16_as_ushort(L1) << 16);
}
__device__ __forceinline__ void unpack2(uint32_t u, float& a, float& b) {
    a = __bfloat162float(__ushort_as_bfloat16((unsigned short)(u & 0xFFFFu)));
    b = __bfloat162float(__ushort_as_bfloat16((unsigned short)(u >> 16)));
}
__device__ __forceinline__ void cp16(uint32_t dst, const void* src) {
    asm volatile("cp.async.cg.shared.global [%0], [%1], 16;" :: "r"(dst), "l"(src));
}
#define CP_COMMIT() asm volatile("cp.async.commit_group;" ::: "memory")
#define CP_WAIT0()  asm volatile("cp.async.wait_group 0;" ::: "memory")

#define LDSM4(r, addr) asm volatile( \
    "ldmatrix.sync.aligned.m8n8.x4.shared.b16 {%0,%1,%2,%3}, [%4];" \
    : "=r"((r)[0]), "=r"((r)[1]), "=r"((r)[2]), "=r"((r)[3]) : "r"(addr))

#define MMA(d, a, b0, b1) asm volatile( \
    "mma.sync.aligned.m16n8k16.row.col.f32.bf16.bf16.f32 " \
    "{%0,%1,%2,%3}, {%4,%5,%6,%7}, {%8,%9}, {%0,%1,%2,%3};" \
    : "+f"((d)[0]), "+f"((d)[1]), "+f"((d)[2]), "+f"((d)[3]) \
    : "r"((a)[0]), "r"((a)[1]), "r"((a)[2]), "r"((a)[3]), "r"(b0), "r"(b1))

// one 16KB chunk [256 n][32 k] bf16 -> smem pitch 80 B (16B-aligned, conflict-free)
__device__ __forceinline__ void copy_chunk(uint32_t dst, const __nv_bfloat16* src, int tid) {
#pragma unroll
    for (int q = 0; q < 4; q++) {
        int u = tid + 256 * q;
        int n = u >> 2, j = u & 3;
        cp16(dst + (uint32_t)(n * 80 + j * 16), src + n * 256 + j * 8);
    }
}

// acc[8][4] += (Ahi+Alo) @ (Whi+Wlo)^T via 3 split products.
// 16 chunks: piece = c>>1 (32k each), split = c&1 (0=hi W, 1=lo W).
__device__ __forceinline__ void do_gemm(float (&acc)[8][4], uint32_t sb,
                                        const __nv_bfloat16* gW,
                                        const __nv_bfloat16* next0, int tid) {
    const int lane = tid & 31, nw = tid >> 5;
    const uint32_t aRow = (uint32_t)((lane & 15) * 528 + (lane >> 4) * 16);
    const uint32_t bRow = (uint32_t)((nw * 32 + (lane & 7)) * 80 + (lane >> 3) * 16);
#pragma unroll 1
    for (int c = 0; c < 16; c++) {
        CP_WAIT0();
        __syncthreads();
        if (c < 15)
            copy_chunk(sb + SB_BUF + (uint32_t)((c + 1) & 1) * 20480u,
                       gW + ((c + 1) & 1) * 65536 + ((c + 1) >> 1) * 32, tid);
        else if (next0)
            copy_chunk(sb + SB_BUF, next0, tid);
        CP_COMMIT();

        const int piece = c >> 1, hiW = !(c & 1);
        const uint32_t bB = sb + SB_BUF + (uint32_t)(c & 1) * 20480u + bRow;
        uint32_t bfr[4][4];
#pragma unroll
        for (int nt = 0; nt < 4; nt++)
            LDSM4(bfr[nt], bB + (uint32_t)(nt * 640));
#pragma unroll
        for (int p = 0; p < 2; p++) {
            if (p == 0 || hiW) {
                uint32_t pl = sb + (uint32_t)((hiW && p == 1) ? SB_HLO : SB_HHI)
                            + aRow + (uint32_t)(piece * 64);
                uint32_t afr[2][2][4];
#pragma unroll
                for (int mg = 0; mg < 2; mg++)
#pragma unroll
                    for (int kt = 0; kt < 2; kt++)
                        LDSM4(afr[mg][kt], pl + (uint32_t)(mg * 8448 + kt * 32));
#pragma unroll
                for (int mg = 0; mg < 2; mg++)
#pragma unroll
                    for (int nt = 0; nt < 4; nt++)
#pragma unroll
                        for (int kt = 0; kt < 2; kt++)
                            MMA(acc[mg * 4 + nt], afr[mg][kt],
                                bfr[nt][2 * kt], bfr[nt][2 * kt + 1]);
            }
        }
    }
    __syncthreads();
}

// ---------------------------------------------------------------- prep kernel
__global__ void prep_kernel(const float* __restrict__ W1, const float* __restrict__ W2,
                            const float* __restrict__ anchors) {
    int stride = gridDim.x * blockDim.x;
    for (int i = blockIdx.x * blockDim.x + threadIdx.x; i < 131072; i += stride) {
        int mat = i >> 16, n = (i >> 8) & 255, k = i & 255;
        float x = (mat ? W2 : W1)[n * 256 + k];
        __nv_bfloat16 hi = __float2bfloat16(x);
        g_Wb[mat * 131072 + n * 256 + k] = hi;
        g_Wb[mat * 131072 + 65536 + n * 256 + k] =
            __float2bfloat16(x - __bfloat162float(hi));
    }
    if (blockIdx.x == 0 && threadIdx.x < 256) {
        float inv[3];
#pragma unroll
        for (int a = 0; a < 3; a++) {
            float ss = 0.f;
            for (int k = 0; k < 256; k++) { float v = anchors[a * 256 + k]; ss += v * v; }
            inv[a] = 1.f / fmaxf(sqrtf(ss), 1e-12f);
        }
        int col = threadIdx.x;
        g_c1[col] = make_float4(anchors[col] * inv[0], anchors[256 + col] * inv[1],
                                anchors[512 + col] * inv[2], 0.f);
    }
}

// ---------------------------------------------------------------- main kernel
__global__ void __launch_bounds__(256, 2)
collapse_mma(const float* __restrict__ h0g, const float* __restrict__ b1g,
             const float* __restrict__ b2g, float* __restrict__ out) {
    extern __shared__ char smb[];
    const uint32_t sb = smem_u32(smb);
    float4*   c1s  = (float4*)(smb + SB_C1);
    float*    b2s  = (float*)(smb + SB_B2);
    float*    stat = (float*)(smb + SB_STAT);
    float*    srow = (float*)(smb + SB_SROW);
    uint32_t* hh   = (uint32_t*)(smb + SB_HHI);   // pitch 132 u32 per row
    uint32_t* hl   = (uint32_t*)(smb + SB_HLO);

    const int tid = threadIdx.x, lane = tid & 31, nw = tid >> 5;
    const int row0 = blockIdx.x * MROWS;

    copy_chunk(sb + SB_BUF, g_Wb, tid);     // GEMM1 chunk 0 (W1 hi, piece 0)
    CP_COMMIT();

    {
        float4 an = g_c1[tid];
        c1s[tid] = make_float4(an.x, an.y, an.z, b1g[tid]);
        b2s[tid] = b2g[tid];
        if (tid < 128) { stat[tid] = 0.f; stat[128 + tid] = 0.f; }
        if (tid < 32) srow[tid] = 1.f;
    }
    __syncthreads();

    // ---- init: h0 -> stats + split planes (8 threads per row, 32 cols each)
    {
        int row = tid >> 3, q = tid & 7;
        const float2* src = (const float2*)(h0g + (size_t)(row0 + row) * 256 + q * 32);
        float p0 = 0, p1 = 0, p2 = 0, p3 = 0;
#pragma unroll
        for (int j = 0; j < 16; j++) {
            float2 v = src[j];
            int col = q * 32 + 2 * j;
            float4 ca = c1s[col], cb = c1s[col + 1];
            p0 += v.x * v.x + v.y * v.y;
            p1 += v.x * ca.x + v.y * cb.x;
            p2 += v.x * ca.y + v.y * cb.y;
            p3 += v.x * ca.z + v.y * cb.z;
            uint32_t ph, pv; split2(v.x, v.y, ph, pv);
            hh[row * 132 + q * 16 + j] = ph;
            hl[row * 132 + q * 16 + j] = pv;
        }
#pragma unroll
        for (int off = 1; off < 8; off <<= 1) {
            p0 += __shfl_xor_sync(~0u, p0, off);
            p1 += __shfl_xor_sync(~0u, p1, off);
            p2 += __shfl_xor_sync(~0u, p2, off);
            p3 += __shfl_xor_sync(~0u, p3, off);
        }
        if ((lane & 7) == 0) {
            atomicAdd(&stat[row], p0);      atomicAdd(&stat[32 + row], p1);
            atomicAdd(&stat[64 + row], p2); atomicAdd(&stat[96 + row], p3);
        }
    }
    __syncthreads();

    float acc[8][4];

#pragma unroll 1
    for (int l = 0; l < NLAYERS; l++) {
        float* stC = stat + (l & 1) * 128;
        float* stN = stat + ((l + 1) & 1) * 128;

        // ---- traces (stats already clip-scaled)
        if (tid < 32) {
            float inv = 1.f / fmaxf(sqrtf(stC[tid]), 1e-12f);
            size_t base = (size_t)(l * B_TOTAL + row0 + tid) * 3;
#pragma unroll
            for (int a = 0; a < 3; a++) {
                float al = stC[(a + 1) * 32 + tid] * inv;
                float dv = 1.f - al;
                out[OUT_ALIGN + base + a] = al;
                out[OUT_DIV + base + a] = dv;
                out[OUT_TEN + base + a] = fabsf(dv);
            }
        }

        // ---- GEMM1: acc = x_unscaled @ W1^T  (prefetches W2 chunk0 at end)
#pragma unroll
        for (int t = 0; t < 8; t++)
#pragma unroll
            for (int e = 0; e < 4; e++) acc[t][e] = 0.f;
        do_gemm(acc, sb, g_Wb, g_Wb + 131072, tid);

        // ---- per-row force coefficients (rows: mg*16 + rh*8 + lane>>2)
        float hmul[4], k0c[4], k1c[4], k2c[4], sR[4];
#pragma unroll
        for (int ridx = 0; ridx < 4; ridx++) {
            int row = (ridx >> 1) * 16 + (ridx & 1) * 8 + (lane >> 2);
            float ss = stC[row], d0 = stC[32 + row], d1 = stC[64 + row], d2 = stC[96 + row];
            float inv = 1.f / fmaxf(sqrtf(ss), 1e-12f);
            float c0 = 0.1f * (1.f - d0 * inv) / fmaxf(sqrtf(fmaxf(ss - 2.f * d0 + 1.f, 0.f)), 1e-12f);
            float c1 = 0.1f * (1.f - d1 * inv) / fmaxf(sqrtf(fmaxf(ss - 2.f * d1 + 1.f, 0.f)), 1e-12f);
            float c2 = 0.1f * (1.f - d2 * inv) / fmaxf(sqrtf(fmaxf(ss - 2.f * d2 + 1.f, 0.f)), 1e-12f);
            k0c[ridx] = c0; k1c[ridx] = c1; k2c[ridx] = c2;
            hmul[ridx] = 1.f - (c0 + c1 + c2);
            sR[ridx] = srow[row];
        }

        // ---- tanh phase: z -> planes; acc := force + b2 (GEMM2 accumulates onto it)
#pragma unroll
        for (int mg = 0; mg < 2; mg++)
#pragma unroll
            for (int nt = 0; nt < 4; nt++) {
                int tile = mg * 4 + nt;
#pragma unroll
                for (int rh = 0; rh < 2; rh++) {
                    int ridx = mg * 2 + rh;
                    int rowi = mg * 16 + rh * 8 + (lane >> 2);
                    int colp = nw * 32 + nt * 8 + (lane & 3) * 2;
                    int hpos = rowi * 132 + (colp >> 1);
                    float4 ca = c1s[colp], cb = c1s[colp + 1];
                    float pre0 = acc[tile][rh * 2 + 0] * sR[ridx] + ca.w;
                    float pre1 = acc[tile][rh * 2 + 1] * sR[ridx] + cb.w;
                    float ha, hb, la, lb;
                    unpack2(hh[hpos], ha, hb); unpack2(hl[hpos], la, lb);
                    float h0v = sR[ridx] * (ha + la), h1v = sR[ridx] * (hb + lb);
                    acc[tile][rh * 2 + 0] = h0v * hmul[ridx] + k0c[ridx] * ca.x
                        + k1c[ridx] * ca.y + k2c[ridx] * ca.z + b2s[colp];
                    acc[tile][rh * 2 + 1] = h1v * hmul[ridx] + k0c[ridx] * cb.x
                        + k1c[ridx] * cb.y + k2c[ridx] * cb.z + b2s[colp + 1];
                    uint32_t ph, pv;
                    split2(fast_tanh(pre0), fast_tanh(pre1), ph, pv);
                    hh[hpos] = ph; hl[hpos] = pv;
                }
            }
        if (tid < 128) stN[tid] = 0.f;

        // ---- GEMM2: acc += z @ W2^T  (prefetches next layer's W1 chunk0)
        do_gemm(acc, sb, g_Wb + 131072,
                (l < NLAYERS - 1) ? g_Wb : (const __nv_bfloat16*)0, tid);

        // ---- epilogue: x = acc; stats; split-store into planes
        {
            float p[4][4];
#pragma unroll
            for (int i = 0; i < 4; i++)
#pragma unroll
                for (int s = 0; s < 4; s++) p[i][s] = 0.f;
#pragma unroll
            for (int mg = 0; mg < 2; mg++)
#pragma unroll
                for (int nt = 0; nt < 4; nt++) {
                    int tile = mg * 4 + nt;
#pragma unroll
                    for (int rh = 0; rh < 2; rh++) {
                        int ridx = mg * 2 + rh;
                        int rowi = mg * 16 + rh * 8 + (lane >> 2);
                        int colp = nw * 32 + nt * 8 + (lane & 3) * 2;
                        float4 ca = c1s[colp], cb = c1s[colp + 1];
                        float x0 = acc[tile][rh * 2 + 0], x1 = acc[tile][rh * 2 + 1];
                        p[ridx][0] += x0 * x0 + x1 * x1;
                        p[ridx][1] += x0 * ca.x + x1 * cb.x;
                        p[ridx][2] += x0 * ca.y + x1 * cb.y;
                        p[ridx][3] += x0 * ca.z + x1 * cb.z;
                        uint32_t ph, pv; split2(x0, x1, ph, pv);
                        hh[rowi * 132 + (colp >> 1)] = ph;
                        hl[rowi * 132 + (colp >> 1)] = pv;
                    }
                }
#pragma unroll
            for (int i = 0; i < 4; i++)
#pragma unroll
                for (int s = 0; s < 4; s++) {
                    p[i][s] += __shfl_xor_sync(~0u, p[i][s], 1);
                    p[i][s] += __shfl_xor_sync(~0u, p[i][s], 2);
                }
            if ((lane & 3) == 0) {
#pragma unroll
                for (int ridx = 0; ridx < 4; ridx++) {
                    int rowi = (ridx >> 1) * 16 + (ridx & 1) * 8 + (lane >> 2);
                    atomicAdd(&stN[rowi], p[ridx][0]);
                    atomicAdd(&stN[32 + rowi], p[ridx][1]);
                    atomicAdd(&stN[64 + rowi], p[ridx][2]);
                    atomicAdd(&stN[96 + rowi], p[ridx][3]);
                }
            }
        }
        __syncthreads();

        // ---- finalize: deferred clip scale; scale stats
        if (tid < 32) {
            float P = stN[tid];
            float n = sqrtf(P);
            float s = (n > 10.f) ? (10.f / (n + 1e-8f)) : 1.f;
            srow[tid] = s;
            stN[tid] = P * s * s;
            stN[32 + tid] *= s; stN[64 + tid] *= s; stN[96 + tid] *= s;
        }
        __syncthreads();
    }

    // ---- store h_final = s * (hi + lo)
    {
        int row = tid >> 3, q = tid & 7;
        float s = srow[row];
        float2* dst = (float2*)(out + (size_t)(row0 + row) * 256 + q * 32);
#pragma unroll
        for (int j = 0; j < 16; j++) {
            float ha, hb, la, lb;
            unpack2(hh[row * 132 + q * 16 + j], ha, hb);
            unpack2(hl[row * 132 + q * 16 + j], la, lb);
            dst[j] = make_float2(s * (ha + la), s * (hb + lb));
        }
    }
}

// ---------------------------------------------------------------- launch
extern "C" void kernel_launch(void* const* d_in, const int* in_sizes, int n_in,
                              void* d_out, int out_size) {
    const float* h0      = (const float*)d_in[0];
    const float* W1      = (const float*)d_in[1];
    const float* b1      = (const float*)d_in[2];
    const float* W2      = (const float*)d_in[3];
    const float* b2      = (const float*)d_in[4];
    const float* anchors = (const float*)d_in[5];
    float* out = (float*)d_out;
    (void)in_sizes; (void)n_in; (void)out_size;

    cudaFuncSetAttribute(collapse_mma,
                         cudaFuncAttributeMaxDynamicSharedMemorySize, SMEM_DYN);

    prep_kernel<<<64, 256>>>(W1, W2, anchors);
    collapse_mma<<<B_TOTAL / MROWS, 256, SMEM_DYN>>>(h0, b1, b2, out);
}